// round 14
// baseline (speedup 1.0000x reference)
#include <cuda_runtime.h>
#include <cuda_bf16.h>
#include <cuda_fp16.h>
#include <cstdint>

#define D_  128
#define H_  132
#define M_  64       // batch rows per tile
#define TPB 384      // 8 compute warps (4 slabs x 2 k-halves) + 4 producer warps
#define NCW 256      // consumer (compute) threads

// ---------------------------------------------------------------------------
// Device-global precomputed buffers
// ---------------------------------------------------------------------------
__device__ float g_Wc[D_ * D_];   // Wu @ Wm
__device__ float g_bc[D_];        // K*(Wu@bm) + bu
// 23 weight chunks (L0:8, L1:5, L2:5, L3:5), each [144 n][40 k] fp16
__device__ __align__(16) __half g_Bw[23][144 * 40];
__device__ float g_biasf[4][144];

// ---------------------------------------------------------------------------
// SMEM map (bytes)
//   A buf0 (hi 33792 | lo 33792)  :      0 .. 67584
//   A buf1                         :  67584 .. 135168
//   B buf0 (fp16, 11520)           : 135168 .. 146688
//   B buf1                         : 146688 .. 158208
//   reduce scratch 4 x 9216        : 158208 .. 195072
// ---------------------------------------------------------------------------
#define ABUFSZ   67584
#define A_LO_OFF 33792
#define ASTRIDE  528
#define B_OFF    135168
#define B_BUF    11520
#define BSTRIDE  80
#define SC_OFF   158208
#define SC_SLAB  9216          // 16 rows x 144 cols x 4B
#define SC_ROW   576           // 144 * 4
#define SMEM_BYTES 195072
#define NCHUNK   23

// ---------------------------------------------------------------------------
// PTX helpers (plain sm_80+ features only)
// ---------------------------------------------------------------------------
__device__ __forceinline__ uint32_t smem_u32(const void* p) {
    uint32_t a;
    asm("{ .reg .u64 t; cvta.to.shared.u64 t, %1; cvt.u32.u64 %0, t; }" : "=r"(a) : "l"(p));
    return a;
}
#define LDSM4(r, a) \
    asm volatile("ldmatrix.sync.aligned.m8n8.x4.shared.b16 {%0,%1,%2,%3}, [%4];" \
                 : "=r"((r)[0]), "=r"((r)[1]), "=r"((r)[2]), "=r"((r)[3]) : "r"(a))
#define LDSM2(r, a) \
    asm volatile("ldmatrix.sync.aligned.m8n8.x2.shared.b16 {%0,%1}, [%2];" \
                 : "=r"((r)[0]), "=r"((r)[1]) : "r"(a))
#define MMA(c, A, Bv) \
    asm volatile("mma.sync.aligned.m16n8k16.row.col.f32.f16.f16.f32 " \
                 "{%0,%1,%2,%3}, {%4,%5,%6,%7}, {%8,%9}, {%0,%1,%2,%3};" \
                 : "+f"((c)[0]), "+f"((c)[1]), "+f"((c)[2]), "+f"((c)[3]) \
                 : "r"((A)[0]), "r"((A)[1]), "r"((A)[2]), "r"((A)[3]), \
                   "r"((Bv)[0]), "r"((Bv)[1]))
#define CP_WAIT0()  asm volatile("cp.async.wait_group 0;" ::: "memory")
#define CP_COMMIT() asm volatile("cp.async.commit_group;" ::: "memory")
#define BAR_CONS()  asm volatile("bar.sync 1, 256;" ::: "memory")

__device__ __forceinline__ uint32_t pack2h(__half a, __half b) {
    uint16_t x = *(uint16_t*)&a, y = *(uint16_t*)&b;
    return (uint32_t)x | ((uint32_t)y << 16);
}
__device__ __forceinline__ void split_f16(float x, __half& h, __half& l) {
    h = __float2half_rn(x);
    l = __float2half_rn(x - __half2float(h));
}

// stage fp16 weight chunk cid into B buf `buf` (720 x 16B, 256 consumer threads)
__device__ __forceinline__ void stage_chunk(uint32_t sb, int cid, int buf, int tid) {
    const char* g = (const char*)&g_Bw[cid][0];
    uint32_t s = sb + B_OFF + (uint32_t)buf * B_BUF;
#pragma unroll
    for (int j = 0; j < 3; j++) {
        int idx = tid + j * NCW;
        if (idx < 720)
            asm volatile("cp.async.cg.shared.global [%0], [%1], 16;"
                         :: "r"(s + idx * 16), "l"(g + idx * 16));
    }
    CP_COMMIT();
}

// ---------------------------------------------------------------------------
// Precompute P1 (measured ~10.5us): Wc = Wu@Wm + bc.
// ---------------------------------------------------------------------------
__global__ void precompWc(const float* __restrict__ Wm, const float* __restrict__ bm,
                          const float* __restrict__ Wu, const float* __restrict__ bu, int K)
{
    extern __shared__ float sWm[];   // 128*128 floats (64 KB)
    __shared__ float sWu[D_];
    const int f = blockIdx.x, tid = threadIdx.x;
    {
        const float4* wm4 = (const float4*)Wm;
        float4* s4 = (float4*)sWm;
        for (int i = tid; i < 4096; i += 128) s4[i] = wm4[i];
    }
    sWu[tid] = Wu[f * D_ + tid];
    __syncthreads();
    float a0 = 0.f, a1 = 0.f, a2 = 0.f, a3 = 0.f;
#pragma unroll
    for (int e = 0; e < D_; e += 4) {
        a0 += sWu[e]     * sWm[e * D_ + tid];
        a1 += sWu[e + 1] * sWm[(e + 1) * D_ + tid];
        a2 += sWu[e + 2] * sWm[(e + 2) * D_ + tid];
        a3 += sWu[e + 3] * sWm[(e + 3) * D_ + tid];
    }
    g_Wc[f * D_ + tid] = (a0 + a1) + (a2 + a3);
    if (tid == 0) {
        float s = 0.f;
        for (int e = 0; e < D_; e++) s += sWu[e] * bm[e];
        g_bc[f] = (float)K * s + bu[f];
    }
}

// ---------------------------------------------------------------------------
// Precompute P2: all 23 fp16 chunks + bias table.
// ---------------------------------------------------------------------------
__global__ void precompChunks(const float* __restrict__ W0, const float* __restrict__ b0,
                              const float* __restrict__ W1, const float* __restrict__ b1,
                              const float* __restrict__ W2, const float* __restrict__ b2,
                              const float* __restrict__ W3, const float* __restrict__ b3)
{
    __shared__ float sm1[128 * 32];   // Wc slice [f][kk]
    __shared__ float sm2[132 * 32];   // folded Wcat slice [n][kk]
    const int cid = blockIdx.x, tid = threadIdx.x;
    int l, c;
    if (cid < 8) { l = 0; c = cid; } else { l = 1 + (cid - 8) / 5; c = (cid - 8) % 5; }

    if (l == 0 && c == 0) {
        for (int t = tid; t < 144; t += 256) {
            float bv = 0.f;
            if (t < H_) {
                bv = b0[t];
                float s0 = 0.f, s1 = 0.f;
#pragma unroll 8
                for (int f = 0; f < 128; f += 2) {
                    s0 += W0[t * 256 + 128 + f]     * g_bc[f];
                    s1 += W0[t * 256 + 128 + f + 1] * g_bc[f + 1];
                }
                bv += s0 + s1;
            }
            g_biasf[0][t] = bv;
        }
    } else if (c == 0) {
        const float* bb = (l == 1) ? b1 : (l == 2) ? b2 : b3;
        const int Nl = (l == 3) ? D_ : H_;
        for (int t = tid; t < 144; t += 256) g_biasf[l][t] = (t < Nl) ? bb[t] : 0.f;
    }

    if (l == 0 && c >= 4) {
        const int base = c * 32 - 128;
        for (int idx = tid; idx < 128 * 32; idx += 256) {
            int f = idx >> 5, kk = idx & 31;
            sm1[idx] = g_Wc[f * D_ + base + kk];
        }
        __syncthreads();
        for (int idx = tid; idx < 132 * 32; idx += 256) {
            int n = idx >> 5, kk = idx & 31;
            float s0 = 0.f, s1 = 0.f;
#pragma unroll 8
            for (int f = 0; f < 128; f += 2) {
                s0 += W0[n * 256 + 128 + f]     * sm1[f * 32 + kk];
                s1 += W0[n * 256 + 128 + f + 1] * sm1[(f + 1) * 32 + kk];
            }
            sm2[idx] = s0 + s1;
        }
        __syncthreads();
    }

    const int Kl = (l == 0) ? 256 : H_;
    const int Nl = (l == 3) ? D_ : H_;
    for (int idx = tid; idx < 144 * 40; idx += 256) {
        int n = idx / 40, kk = idx % 40;
        int k = c * 32 + kk;
        float w = 0.f;
        if (kk < 32 && n < Nl && k < Kl) {
            if (l == 0)      w = (c < 4) ? W0[n * 256 + k] : sm2[n * 32 + kk];
            else if (l == 1) w = W1[n * H_ + k];
            else if (l == 2) w = W2[n * H_ + k];
            else             w = W3[n * H_ + k];
        }
        g_Bw[cid][idx] = __float2half_rn(w);
    }
}

// ---------------------------------------------------------------------------
// A-tile loader: signal cols 0-127, csum cols 128-255, split hi/lo fp16.
// ---------------------------------------------------------------------------
__device__ __forceinline__ void load_tile(char* smem, int abase, long rbase,
                                          const float4* __restrict__ sig4,
                                          const float4* __restrict__ cmp4,
                                          long sK, int t0, int nthr)
{
    for (int idx = t0; idx < 2048; idx += nthr) {
        int half = idx >> 10, t = idx & 1023;
        int r = t >> 4, g = t & 15;
        long ga = (rbase + r) * 32 + g * 2;
        float4 v0, v1;
        if (half == 0) { v0 = sig4[ga]; v1 = sig4[ga + 1]; }
        else {
            v0 = make_float4(0.f, 0.f, 0.f, 0.f); v1 = v0;
#pragma unroll 8
            for (int k = 0; k < 8; k++) {
                float4 a = cmp4[ga + (long)k * sK];
                float4 b = cmp4[ga + 1 + (long)k * sK];
                v0.x += a.x; v0.y += a.y; v0.z += a.z; v0.w += a.w;
                v1.x += b.x; v1.y += b.y; v1.z += b.z; v1.w += b.w;
            }
        }
        float f[8] = {v0.x, v0.y, v0.z, v0.w, v1.x, v1.y, v1.z, v1.w};
        uint32_t hh[4], ll[4];
#pragma unroll
        for (int j = 0; j < 4; j++) {
            __half h0, l0, h1, l1;
            split_f16(f[2 * j], h0, l0);
            split_f16(f[2 * j + 1], h1, l1);
            hh[j] = pack2h(h0, h1);
            ll[j] = pack2h(l0, l1);
        }
        int cols = half * 128 + g * 8;
        *(uint4*)(smem + abase + r * ASTRIDE + cols * 2)            = make_uint4(hh[0], hh[1], hh[2], hh[3]);
        *(uint4*)(smem + abase + A_LO_OFF + r * ASTRIDE + cols * 2) = make_uint4(ll[0], ll[1], ll[2], ll[3]);
    }
}

// ---------------------------------------------------------------------------
// One layer. 8 compute warps: warp w -> row slab (w&3)*16, k-half w>>2.
// Each warp processes only its k16-half of each chunk (loads partitioned,
// not duplicated). Layer-end fp32 reduction through smem scratch; k-half-0
// warps apply bias/ReLU and write next-layer activations.
// ---------------------------------------------------------------------------
template<int NT, int NC, bool RELU, bool LAST, bool ZPAD>
__device__ __forceinline__ void run_layer(char* smem, uint32_t sb, int layer, int& cid,
                                          int par, bool more,
                                          int abase, int tid, int wid, int lane,
                                          float* __restrict__ gout)
{
    constexpr int GS = 6;
    constexpr int NG = (NT + GS - 1) / GS;

    float acc[NT][4];
#pragma unroll
    for (int t = 0; t < NT; t++)
#pragma unroll
        for (int j = 0; j < 4; j++) acc[t][j] = 0.f;

    const int slab = wid & 3;
    const int g2   = wid >> 2;          // k-half: 0 or 1
    const int R0 = slab * 16;
    const int ln = lane & 15;
    const uint32_t kso  = (uint32_t)g2 * 32;   // byte offset of this warp's k16-half
    const uint32_t aAh0 = sb + abase + (uint32_t)(R0 + ln) * ASTRIDE + (uint32_t)(lane >> 4) * 16;
    const uint32_t bB0  = sb + B_OFF + (uint32_t)(ln & 7) * BSTRIDE + (uint32_t)(ln >> 3) * 16;

    for (int c = 0; c < NC; c++) {
        CP_WAIT0();            // chunk cid staged
        BAR_CONS();            // all compute warps done with the other B buf
        {
            int nb = cid + 1;
            if (nb < NCHUNK)   stage_chunk(sb, nb, (par + nb) & 1, tid);
            else if (more)     stage_chunk(sb, 0,  (par + nb) & 1, tid);
        }
        const uint32_t bbuf = bB0 + (uint32_t)((par + cid) & 1) * B_BUF + kso;
        const uint32_t ak   = aAh0 + (uint32_t)c * 64 + kso;

        uint32_t Ah[4], Al[4];
        LDSM4(Ah, ak);
        LDSM4(Al, ak + A_LO_OFF);

        uint32_t Bf[2][GS][2];
#pragma unroll
        for (int j = 0; j < GS; j++)
            if (j < NT) LDSM2(Bf[0][j], bbuf + (uint32_t)j * (8 * BSTRIDE));
#pragma unroll
        for (int g = 0; g < NG; g++) {
            const int cu = g & 1, nx = cu ^ 1;
            if (g + 1 < NG) {
#pragma unroll
                for (int j = 0; j < GS; j++) {
                    const int t = (g + 1) * GS + j;
                    if (t < NT) LDSM2(Bf[nx][j], bbuf + (uint32_t)t * (8 * BSTRIDE));
                }
            }
#pragma unroll
            for (int j = 0; j < GS; j++) {
                const int t = g * GS + j;
                if (t < NT) MMA(acc[t], Ah, Bf[cu][j]);
            }
#pragma unroll
            for (int j = 0; j < GS; j++) {
                const int t = g * GS + j;
                if (t < NT) MMA(acc[t], Al, Bf[cu][j]);
            }
        }
        cid++;
    }

    // ---- cross-k-half reduction through smem scratch
    const int rq = lane >> 2;                 // 0..7
    const int cq = (lane & 3) * 2;
    char* sc = smem + SC_OFF + slab * SC_SLAB;
    if (g2 == 1) {
#pragma unroll
        for (int t = 0; t < NT; t++) {
            const int col = t * 8 + cq;
            *(float2*)(sc + rq * SC_ROW + col * 4)       = make_float2(acc[t][0], acc[t][1]);
            *(float2*)(sc + (rq + 8) * SC_ROW + col * 4) = make_float2(acc[t][2], acc[t][3]);
        }
    }
    BAR_CONS();

    if (g2 == 0) {
        const float* bias = &g_biasf[layer][0];
        const int r0 = R0 + rq;
#pragma unroll
        for (int t = 0; t < NT; t++) {
            const int col = t * 8 + cq;
            float2 p0 = *(float2*)(sc + rq * SC_ROW + col * 4);
            float2 p1 = *(float2*)(sc + (rq + 8) * SC_ROW + col * 4);
            const float b0 = __ldg(bias + col), b1 = __ldg(bias + col + 1);
            float v00 = acc[t][0] + p0.x + b0, v01 = acc[t][1] + p0.y + b1;
            float v10 = acc[t][2] + p1.x + b0, v11 = acc[t][3] + p1.y + b1;
            if (RELU) {
                v00 = fmaxf(v00, 0.f); v01 = fmaxf(v01, 0.f);
                v10 = fmaxf(v10, 0.f); v11 = fmaxf(v11, 0.f);
            }
            if (LAST) {
                *(float2*)(gout + (long)r0 * D_ + col)       = make_float2(v00, v01);
                *(float2*)(gout + (long)(r0 + 8) * D_ + col) = make_float2(v10, v11);
            } else {
                __half h0, l0, h1, l1;
                split_f16(v00, h0, l0); split_f16(v01, h1, l1);
                *(uint32_t*)(smem + abase + r0 * ASTRIDE + col * 2)            = pack2h(h0, h1);
                *(uint32_t*)(smem + abase + A_LO_OFF + r0 * ASTRIDE + col * 2) = pack2h(l0, l1);
                split_f16(v10, h0, l0); split_f16(v11, h1, l1);
                *(uint32_t*)(smem + abase + (r0 + 8) * ASTRIDE + col * 2)            = pack2h(h0, h1);
                *(uint32_t*)(smem + abase + A_LO_OFF + (r0 + 8) * ASTRIDE + col * 2) = pack2h(l0, l1);
            }
        }
        if (ZPAD) {   // zero activation K-pad cols 144..159 (hi & lo)
            const int zr = R0 + (lane >> 1);
            const int zc = 144 + (lane & 1) * 8;
            uint4 z = make_uint4(0u, 0u, 0u, 0u);
            *(uint4*)(smem + abase + zr * ASTRIDE + zc * 2)            = z;
            *(uint4*)(smem + abase + A_LO_OFF + zr * ASTRIDE + zc * 2) = z;
        }
    }
    __syncwarp();
    // next layer's first BAR_CONS orders epilogue A-writes before k-half-1 reads
}

// ---------------------------------------------------------------------------
// Persistent kernel: warps 0-7 compute (k-split), warps 8-11 load next tile
// ---------------------------------------------------------------------------
__global__ __launch_bounds__(TPB, 1)
void fused_mma(const float* __restrict__ sig, const float* __restrict__ comps,
               float* __restrict__ out, int Bn, int K)
{
    extern __shared__ __align__(16) char smem[];
    const uint32_t sb = smem_u32(smem);
    const int tid = threadIdx.x, wid = tid >> 5, lane = tid & 31;
    const int G = gridDim.x;
    const int ntiles = Bn / M_;

    const float4* sig4 = (const float4*)sig;
    const float4* cmp4 = (const float4*)comps;
    const long sK = (long)Bn * 32;

    // prologue: all 384 threads load first tile; consumers stage chunk 0
    load_tile(smem, 0, (long)blockIdx.x * M_, sig4, cmp4, sK, tid, TPB);
    if (tid < NCW) stage_chunk(sb, 0, 0, tid);
    __syncthreads();

    int i = 0;
    for (int t = blockIdx.x; t < ntiles; t += G, i++) {
        if (tid < NCW) {
            const int par = i & 1;
            const int abase = (i & 1) * ABUFSZ;
            const bool more = (t + G < ntiles);
            float* gout = out + (long)t * M_ * D_;
            int cid = 0;
            run_layer<18, 8, true,  false, true >(smem, sb, 0, cid, par, true, abase, tid, wid, lane, nullptr);
            run_layer<18, 5, true,  false, false>(smem, sb, 1, cid, par, true, abase, tid, wid, lane, nullptr);
            run_layer<18, 5, true,  false, false>(smem, sb, 2, cid, par, true, abase, tid, wid, lane, nullptr);
            run_layer<16, 5, false, true,  false>(smem, sb, 3, cid, par, more, abase, tid, wid, lane, gout);
        } else {
            long tn = (long)t + G;
            if (tn < ntiles)
                load_tile(smem, ((i + 1) & 1) * ABUFSZ, tn * M_, sig4, cmp4, sK, tid - NCW, TPB - NCW);
        }
        __syncthreads();   // tile boundary: A buffers exchange ownership
    }
}

// ---------------------------------------------------------------------------
extern "C" void kernel_launch(void* const* d_in, const int* in_sizes, int n_in,
                              void* d_out, int out_size)
{
    const float* sig   = (const float*)d_in[0];
    const float* comps = (const float*)d_in[1];
    const float* Wm    = (const float*)d_in[2];
    const float* bm    = (const float*)d_in[3];
    const float* Wu    = (const float*)d_in[4];
    const float* bu    = (const float*)d_in[5];
    const float* W0    = (const float*)d_in[6];
    const float* b0    = (const float*)d_in[7];
    const float* W1    = (const float*)d_in[8];
    const float* b1    = (const float*)d_in[9];
    const float* W2    = (const float*)d_in[10];
    const float* b2    = (const float*)d_in[11];
    const float* W3    = (const float*)d_in[12];
    const float* b3    = (const float*)d_in[13];
    float* out = (float*)d_out;

    const int B = in_sizes[0] / D_;           // 65536
    const int K = in_sizes[1] / in_sizes[0];  // 8

    int nsm = 148;
    cudaDeviceGetAttribute(&nsm, cudaDevAttrMultiProcessorCount, 0);

    cudaFuncSetAttribute(fused_mma,
                         cudaFuncAttributeMaxDynamicSharedMemorySize, SMEM_BYTES);
    cudaFuncSetAttribute(precompWc,
                         cudaFuncAttributeMaxDynamicSharedMemorySize, 65536);

    precompWc<<<D_, D_, 65536>>>(Wm, bm, Wu, bu, K);
    precompChunks<<<NCHUNK, 256>>>(W0, b0, W1, b1, W2, b2, W3, b3);
    fused_mma<<<nsm, TPB, SMEM_BYTES>>>(sig, comps, out, B, K);
}

// round 15
// speedup vs baseline: 1.0194x; 1.0194x over previous
#include <cuda_runtime.h>
#include <cuda_bf16.h>
#include <cuda_fp16.h>
#include <cstdint>

#define D_  128
#define H_  132
#define M_  64       // batch rows per CTA
#define TPB 128      // 4 warps; 2 CTAs co-resident per SM

// ---------------------------------------------------------------------------
// Device-global precomputed buffers
// ---------------------------------------------------------------------------
__device__ float g_Wc[D_ * D_];   // Wu @ Wm
__device__ float g_bc[D_];        // K*(Wu@bm) + bu
// 23 weight chunks (L0:8, L1:5, L2:5, L3:5), each [144 n][40 k] fp16
__device__ __align__(16) __half g_Bw[23][144 * 40];
__device__ float g_biasf[4][144];

// ---------------------------------------------------------------------------
// SMEM map (bytes)
//   A hi [64][264] fp16 (row stride 528B) :      0 .. 33792
//   A lo                                   :  33792 .. 67584
//   B buf0 (fp16, 11520)                   :  67584 .. 79104
//   B buf1                                 :  79104 .. 90624
// ---------------------------------------------------------------------------
#define A_LO_OFF 33792
#define ASTRIDE  528
#define B_OFF    67584
#define B_BUF    11520
#define BSTRIDE  80
#define SMEM_BYTES 90624
#define NCHUNK   23

// ---------------------------------------------------------------------------
// PTX helpers (plain sm_80+ features only)
// ---------------------------------------------------------------------------
__device__ __forceinline__ uint32_t smem_u32(const void* p) {
    uint32_t a;
    asm("{ .reg .u64 t; cvta.to.shared.u64 t, %1; cvt.u32.u64 %0, t; }" : "=r"(a) : "l"(p));
    return a;
}
#define LDSM4(r, a) \
    asm volatile("ldmatrix.sync.aligned.m8n8.x4.shared.b16 {%0,%1,%2,%3}, [%4];" \
                 : "=r"((r)[0]), "=r"((r)[1]), "=r"((r)[2]), "=r"((r)[3]) : "r"(a))
#define LDSM2(r, a) \
    asm volatile("ldmatrix.sync.aligned.m8n8.x2.shared.b16 {%0,%1}, [%2];" \
                 : "=r"((r)[0]), "=r"((r)[1]) : "r"(a))
#define MMA(c, A, Bv) \
    asm volatile("mma.sync.aligned.m16n8k16.row.col.f32.f16.f16.f32 " \
                 "{%0,%1,%2,%3}, {%4,%5,%6,%7}, {%8,%9}, {%0,%1,%2,%3};" \
                 : "+f"((c)[0]), "+f"((c)[1]), "+f"((c)[2]), "+f"((c)[3]) \
                 : "r"((A)[0]), "r"((A)[1]), "r"((A)[2]), "r"((A)[3]), \
                   "r"((Bv)[0]), "r"((Bv)[1]))
#define CP_WAIT0()  asm volatile("cp.async.wait_group 0;" ::: "memory")
#define CP_COMMIT() asm volatile("cp.async.commit_group;" ::: "memory")

__device__ __forceinline__ uint32_t pack2h(__half a, __half b) {
    uint16_t x = *(uint16_t*)&a, y = *(uint16_t*)&b;
    return (uint32_t)x | ((uint32_t)y << 16);
}
__device__ __forceinline__ void split_f16(float x, __half& h, __half& l) {
    h = __float2half_rn(x);
    l = __float2half_rn(x - __half2float(h));
}

// stage fp16 weight chunk cid into B buf `buf` (720 x 16B, 128 threads)
__device__ __forceinline__ void stage_chunk(uint32_t sb, int cid, int buf, int tid) {
    const char* g = (const char*)&g_Bw[cid][0];
    uint32_t s = sb + B_OFF + (uint32_t)buf * B_BUF;
#pragma unroll
    for (int j = 0; j < 6; j++) {
        int idx = tid + j * TPB;
        if (idx < 720)
            asm volatile("cp.async.cg.shared.global [%0], [%1], 16;"
                         :: "r"(s + idx * 16), "l"(g + idx * 16));
    }
    CP_COMMIT();
}

// ---------------------------------------------------------------------------
// Precompute P1 (measured ~10.5us): Wc = Wu@Wm + bc.
// ---------------------------------------------------------------------------
__global__ void precompWc(const float* __restrict__ Wm, const float* __restrict__ bm,
                          const float* __restrict__ Wu, const float* __restrict__ bu, int K)
{
    extern __shared__ float sWm[];   // 128*128 floats (64 KB)
    __shared__ float sWu[D_];
    const int f = blockIdx.x, tid = threadIdx.x;
    {
        const float4* wm4 = (const float4*)Wm;
        float4* s4 = (float4*)sWm;
        for (int i = tid; i < 4096; i += 128) s4[i] = wm4[i];
    }
    sWu[tid] = Wu[f * D_ + tid];
    __syncthreads();
    float a0 = 0.f, a1 = 0.f, a2 = 0.f, a3 = 0.f;
#pragma unroll
    for (int e = 0; e < D_; e += 4) {
        a0 += sWu[e]     * sWm[e * D_ + tid];
        a1 += sWu[e + 1] * sWm[(e + 1) * D_ + tid];
        a2 += sWu[e + 2] * sWm[(e + 2) * D_ + tid];
        a3 += sWu[e + 3] * sWm[(e + 3) * D_ + tid];
    }
    g_Wc[f * D_ + tid] = (a0 + a1) + (a2 + a3);
    if (tid == 0) {
        float s = 0.f;
        for (int e = 0; e < D_; e++) s += sWu[e] * bm[e];
        g_bc[f] = (float)K * s + bu[f];
    }
}

// ---------------------------------------------------------------------------
// Precompute P2: all 23 fp16 chunks + bias table.
// ---------------------------------------------------------------------------
__global__ void precompChunks(const float* __restrict__ W0, const float* __restrict__ b0,
                              const float* __restrict__ W1, const float* __restrict__ b1,
                              const float* __restrict__ W2, const float* __restrict__ b2,
                              const float* __restrict__ W3, const float* __restrict__ b3)
{
    __shared__ float sm1[128 * 32];   // Wc slice [f][kk]
    __shared__ float sm2[132 * 32];   // folded Wcat slice [n][kk]
    const int cid = blockIdx.x, tid = threadIdx.x;
    int l, c;
    if (cid < 8) { l = 0; c = cid; } else { l = 1 + (cid - 8) / 5; c = (cid - 8) % 5; }

    if (l == 0 && c == 0) {
        for (int t = tid; t < 144; t += 256) {
            float bv = 0.f;
            if (t < H_) {
                bv = b0[t];
                float s0 = 0.f, s1 = 0.f;
#pragma unroll 8
                for (int f = 0; f < 128; f += 2) {
                    s0 += W0[t * 256 + 128 + f]     * g_bc[f];
                    s1 += W0[t * 256 + 128 + f + 1] * g_bc[f + 1];
                }
                bv += s0 + s1;
            }
            g_biasf[0][t] = bv;
        }
    } else if (c == 0) {
        const float* bb = (l == 1) ? b1 : (l == 2) ? b2 : b3;
        const int Nl = (l == 3) ? D_ : H_;
        for (int t = tid; t < 144; t += 256) g_biasf[l][t] = (t < Nl) ? bb[t] : 0.f;
    }

    if (l == 0 && c >= 4) {
        const int base = c * 32 - 128;
        for (int idx = tid; idx < 128 * 32; idx += 256) {
            int f = idx >> 5, kk = idx & 31;
            sm1[idx] = g_Wc[f * D_ + base + kk];
        }
        __syncthreads();
        for (int idx = tid; idx < 132 * 32; idx += 256) {
            int n = idx >> 5, kk = idx & 31;
            float s0 = 0.f, s1 = 0.f;
#pragma unroll 8
            for (int f = 0; f < 128; f += 2) {
                s0 += W0[n * 256 + 128 + f]     * sm1[f * 32 + kk];
                s1 += W0[n * 256 + 128 + f + 1] * sm1[(f + 1) * 32 + kk];
            }
            sm2[idx] = s0 + s1;
        }
        __syncthreads();
    }

    const int Kl = (l == 0) ? 256 : H_;
    const int Nl = (l == 3) ? D_ : H_;
    for (int idx = tid; idx < 144 * 40; idx += 256) {
        int n = idx / 40, kk = idx % 40;
        int k = c * 32 + kk;
        float w = 0.f;
        if (kk < 32 && n < Nl && k < Kl) {
            if (l == 0)      w = (c < 4) ? W0[n * 256 + k] : sm2[n * 32 + kk];
            else if (l == 1) w = W1[n * H_ + k];
            else if (l == 2) w = W2[n * H_ + k];
            else             w = W3[n * H_ + k];
        }
        g_Bw[cid][idx] = __float2half_rn(w);
    }
}

// ---------------------------------------------------------------------------
// One layer (4 warps, 16-row slab each, all N). 2-term fp16 with the two
// dependent MMAs on each acc[t] separated into two passes per GS=6 group.
// ---------------------------------------------------------------------------
template<int NT, int NC, bool RELU, bool LAST, bool ZPAD>
__device__ __forceinline__ void run_layer(char* smem, uint32_t sb, int layer, int& cid,
                                          int tid, int wid, int lane,
                                          float* __restrict__ gout)
{
    constexpr int GS = 6;
    constexpr int NG = (NT + GS - 1) / GS;

    float acc[NT][4];
#pragma unroll
    for (int t = 0; t < NT; t++)
#pragma unroll
        for (int j = 0; j < 4; j++) acc[t][j] = 0.f;

    const int R0 = wid * 16;
    const int ln = lane & 15;
    const uint32_t aAh0 = sb + (uint32_t)(R0 + ln) * ASTRIDE + (uint32_t)(lane >> 4) * 16;
    const uint32_t bB0  = sb + B_OFF + (uint32_t)(ln & 7) * BSTRIDE + (uint32_t)(ln >> 3) * 16;

    for (int c = 0; c < NC; c++) {
        CP_WAIT0();            // chunk cid staged
        __syncthreads();       // all warps done with the other B buf
        {
            int nb = cid + 1;
            if (nb < NCHUNK) stage_chunk(sb, nb, nb & 1, tid);
        }
        const uint32_t bbuf = bB0 + (uint32_t)(cid & 1) * B_BUF;
        const uint32_t ak   = aAh0 + (uint32_t)c * 64;
#pragma unroll
        for (int s = 0; s < 2; s++) {
            uint32_t Ah[4], Al[4];
            LDSM4(Ah, ak + s * 32);
            LDSM4(Al, ak + s * 32 + A_LO_OFF);

            uint32_t Bf[2][GS][2];
#pragma unroll
            for (int j = 0; j < GS; j++)
                if (j < NT) LDSM2(Bf[0][j], bbuf + (uint32_t)j * (8 * BSTRIDE) + s * 32);
#pragma unroll
            for (int g = 0; g < NG; g++) {
                const int cu = g & 1, nx = cu ^ 1;
                if (g + 1 < NG) {
#pragma unroll
                    for (int j = 0; j < GS; j++) {
                        const int t = (g + 1) * GS + j;
                        if (t < NT) LDSM2(Bf[nx][j], bbuf + (uint32_t)t * (8 * BSTRIDE) + s * 32);
                    }
                }
                // pass 1: all Ah MMAs of this group (mutually independent)
#pragma unroll
                for (int j = 0; j < GS; j++) {
                    const int t = g * GS + j;
                    if (t < NT) MMA(acc[t], Ah, Bf[cu][j]);
                }
                // pass 2: all Al MMAs (6 issue slots after their RAW producers)
#pragma unroll
                for (int j = 0; j < GS; j++) {
                    const int t = g * GS + j;
                    if (t < NT) MMA(acc[t], Al, Bf[cu][j]);
                }
            }
        }
        cid++;
    }

    // ---- epilogue (warp-private rows); bias via LDG (L2-resident)
    const float* bias = &g_biasf[layer][0];
    const int r0 = R0 + (lane >> 2);
#pragma unroll
    for (int t = 0; t < NT; t++) {
        const int col = t * 8 + (lane & 3) * 2;
        const float b0 = __ldg(bias + col), b1 = __ldg(bias + col + 1);
        float v00 = acc[t][0] + b0, v01 = acc[t][1] + b1;
        float v10 = acc[t][2] + b0, v11 = acc[t][3] + b1;
        if (RELU) {
            v00 = fmaxf(v00, 0.f); v01 = fmaxf(v01, 0.f);
            v10 = fmaxf(v10, 0.f); v11 = fmaxf(v11, 0.f);
        }
        if (LAST) {
            *(float2*)(gout + (long)r0 * D_ + col)       = make_float2(v00, v01);
            *(float2*)(gout + (long)(r0 + 8) * D_ + col) = make_float2(v10, v11);
        } else {
            __half h0, l0, h1, l1;
            split_f16(v00, h0, l0); split_f16(v01, h1, l1);
            *(uint32_t*)(smem + r0 * ASTRIDE + col * 2)            = pack2h(h0, h1);
            *(uint32_t*)(smem + A_LO_OFF + r0 * ASTRIDE + col * 2) = pack2h(l0, l1);
            split_f16(v10, h0, l0); split_f16(v11, h1, l1);
            *(uint32_t*)(smem + (r0 + 8) * ASTRIDE + col * 2)            = pack2h(h0, h1);
            *(uint32_t*)(smem + A_LO_OFF + (r0 + 8) * ASTRIDE + col * 2) = pack2h(l0, l1);
        }
    }
    if (ZPAD) {   // zero activation K-pad cols 144..159 (hi & lo)
        const int zr = R0 + (lane >> 1);
        const int zc = 144 + (lane & 1) * 8;
        uint4 z = make_uint4(0u, 0u, 0u, 0u);
        *(uint4*)(smem + zr * ASTRIDE + zc * 2)            = z;
        *(uint4*)(smem + A_LO_OFF + zr * ASTRIDE + zc * 2) = z;
    }
    __syncwarp();   // next layer's ldmatrix reads lanes' cross-written rows
}

// ---------------------------------------------------------------------------
// Main kernel: one M=64 tile per CTA, 4 warps, 2 CTAs co-resident per SM.
// ---------------------------------------------------------------------------
__global__ __launch_bounds__(TPB, 2)
void fused_mma(const float* __restrict__ sig, const float* __restrict__ comps,
               float* __restrict__ out, int Bn, int K)
{
    extern __shared__ __align__(16) char smem[];
    const uint32_t sb = smem_u32(smem);
    const int tid = threadIdx.x, wid = tid >> 5, lane = tid & 31;
    const long rbase = (long)blockIdx.x * M_;

    stage_chunk(sb, 0, 0, tid);   // prefetch first weight chunk

    // ---- tile load: cols 0-127 signal, 128-255 csum; split hi/lo fp16
    {
        const float4* sig4 = (const float4*)sig;
        const float4* cmp4 = (const float4*)comps;
        const long sK = (long)Bn * 32;
        for (int idx = tid; idx < 2048; idx += TPB) {
            int half = idx >> 10, t = idx & 1023;
            int r = t >> 4, g = t & 15;
            long ga = (rbase + r) * 32 + g * 2;
            float4 v0, v1;
            if (half == 0) { v0 = sig4[ga]; v1 = sig4[ga + 1]; }
            else {
                v0 = make_float4(0.f, 0.f, 0.f, 0.f); v1 = v0;
#pragma unroll 8
                for (int k = 0; k < 8; k++) {
                    float4 a = cmp4[ga + (long)k * sK];
                    float4 b = cmp4[ga + 1 + (long)k * sK];
                    v0.x += a.x; v0.y += a.y; v0.z += a.z; v0.w += a.w;
                    v1.x += b.x; v1.y += b.y; v1.z += b.z; v1.w += b.w;
                }
            }
            float f[8] = {v0.x, v0.y, v0.z, v0.w, v1.x, v1.y, v1.z, v1.w};
            uint32_t hh[4], ll[4];
#pragma unroll
            for (int j = 0; j < 4; j++) {
                __half h0, l0, h1, l1;
                split_f16(f[2 * j], h0, l0);
                split_f16(f[2 * j + 1], h1, l1);
                hh[j] = pack2h(h0, h1);
                ll[j] = pack2h(l0, l1);
            }
            int cols = half * 128 + g * 8;
            *(uint4*)(smem + r * ASTRIDE + cols * 2)            = make_uint4(hh[0], hh[1], hh[2], hh[3]);
            *(uint4*)(smem + A_LO_OFF + r * ASTRIDE + cols * 2) = make_uint4(ll[0], ll[1], ll[2], ll[3]);
        }
    }
    // (first CP_WAIT0 + __syncthreads inside run_layer orders A stores)

    int cid = 0;
    float* gout = out + rbase * D_;
    run_layer<18, 8, true,  false, true >(smem, sb, 0, cid, tid, wid, lane, nullptr);
    run_layer<18, 5, true,  false, false>(smem, sb, 1, cid, tid, wid, lane, nullptr);
    run_layer<18, 5, true,  false, false>(smem, sb, 2, cid, tid, wid, lane, nullptr);
    run_layer<16, 5, false, true,  false>(smem, sb, 3, cid, tid, wid, lane, gout);
}

// ---------------------------------------------------------------------------
extern "C" void kernel_launch(void* const* d_in, const int* in_sizes, int n_in,
                              void* d_out, int out_size)
{
    const float* sig   = (const float*)d_in[0];
    const float* comps = (const float*)d_in[1];
    const float* Wm    = (const float*)d_in[2];
    const float* bm    = (const float*)d_in[3];
    const float* Wu    = (const float*)d_in[4];
    const float* bu    = (const float*)d_in[5];
    const float* W0    = (const float*)d_in[6];
    const float* b0    = (const float*)d_in[7];
    const float* W1    = (const float*)d_in[8];
    const float* b1    = (const float*)d_in[9];
    const float* W2    = (const float*)d_in[10];
    const float* b2    = (const float*)d_in[11];
    const float* W3    = (const float*)d_in[12];
    const float* b3    = (const float*)d_in[13];
    float* out = (float*)d_out;

    const int B = in_sizes[0] / D_;           // 65536
    const int K = in_sizes[1] / in_sizes[0];  // 8

    cudaFuncSetAttribute(fused_mma,
                         cudaFuncAttributeMaxDynamicSharedMemorySize, SMEM_BYTES);
    cudaFuncSetAttribute(precompWc,
                         cudaFuncAttributeMaxDynamicSharedMemorySize, 65536);

    precompWc<<<D_, D_, 65536>>>(Wm, bm, Wu, bu, K);
    precompChunks<<<NCHUNK, 256>>>(W0, b0, W1, b1, W2, b2, W3, b3);
    fused_mma<<<B / M_, TPB, SMEM_BYTES>>>(sig, comps, out, B, K);
}

// round 16
// speedup vs baseline: 1.1434x; 1.1216x over previous
#include <cuda_runtime.h>
#include <cuda_bf16.h>
#include <cuda_fp16.h>
#include <cstdint>

#define D_  128
#define H_  132
#define M_  64       // batch rows per tile
#define TPB 256      // 4 compute warps + 4 producer warps

// ---------------------------------------------------------------------------
// Device-global precomputed buffers
// ---------------------------------------------------------------------------
__device__ float g_Wc[D_ * D_];   // Wu @ Wm
__device__ float g_bc[D_];        // K*(Wu@bm) + bu
// 23 weight chunks (L0:8, L1:5, L2:5, L3:5), each [144 n][40 k] fp16
__device__ __align__(16) __half g_Bw[23][144 * 40];
__device__ float g_biasf[4][144];

// ---------------------------------------------------------------------------
// SMEM map (bytes)
//   A buf0 (hi 33792 | lo 33792)  :      0 .. 67584
//   A buf1                         :  67584 .. 135168
//   B buf x3 (fp16, 11520 each)    : 135168 .. 169728
//   bias [4][144] f32              : 169728 .. 172032
// ---------------------------------------------------------------------------
#define ABUFSZ   67584
#define A_LO_OFF 33792
#define ASTRIDE  528
#define B_OFF    135168
#define B_BUF    11520
#define BSTRIDE  80
#define BIAS_OFF 169728
#define SMEM_BYTES 172032
#define NCHUNK   23

// ---------------------------------------------------------------------------
// PTX helpers (plain sm_80+ features only)
// ---------------------------------------------------------------------------
__device__ __forceinline__ uint32_t smem_u32(const void* p) {
    uint32_t a;
    asm("{ .reg .u64 t; cvta.to.shared.u64 t, %1; cvt.u32.u64 %0, t; }" : "=r"(a) : "l"(p));
    return a;
}
#define LDSM4(r, a) \
    asm volatile("ldmatrix.sync.aligned.m8n8.x4.shared.b16 {%0,%1,%2,%3}, [%4];" \
                 : "=r"((r)[0]), "=r"((r)[1]), "=r"((r)[2]), "=r"((r)[3]) : "r"(a))
#define LDSM2(r, a) \
    asm volatile("ldmatrix.sync.aligned.m8n8.x2.shared.b16 {%0,%1}, [%2];" \
                 : "=r"((r)[0]), "=r"((r)[1]) : "r"(a))
#define MMA(c, A, Bv) \
    asm volatile("mma.sync.aligned.m16n8k16.row.col.f32.f16.f16.f32 " \
                 "{%0,%1,%2,%3}, {%4,%5,%6,%7}, {%8,%9}, {%0,%1,%2,%3};" \
                 : "+f"((c)[0]), "+f"((c)[1]), "+f"((c)[2]), "+f"((c)[3]) \
                 : "r"((A)[0]), "r"((A)[1]), "r"((A)[2]), "r"((A)[3]), \
                   "r"((Bv)[0]), "r"((Bv)[1]))
#define CP_WAIT1()  asm volatile("cp.async.wait_group 1;" ::: "memory")
#define CP_COMMIT() asm volatile("cp.async.commit_group;" ::: "memory")
#define BAR_CONS()  asm volatile("bar.sync 1, 128;" ::: "memory")

__device__ __forceinline__ uint32_t pack2h(__half a, __half b) {
    uint16_t x = *(uint16_t*)&a, y = *(uint16_t*)&b;
    return (uint32_t)x | ((uint32_t)y << 16);
}
__device__ __forceinline__ void split_f16(float x, __half& h, __half& l) {
    h = __float2half_rn(x);
    l = __float2half_rn(x - __half2float(h));
}

// stage fp16 weight chunk cid into B buf `buf` (720 x 16B, 128 consumer threads)
__device__ __forceinline__ void stage_chunk(uint32_t sb, int cid, int buf, int tid128) {
    const char* g = (const char*)&g_Bw[cid][0];
    uint32_t s = sb + B_OFF + (uint32_t)buf * B_BUF;
#pragma unroll
    for (int j = 0; j < 6; j++) {
        int idx = tid128 + j * 128;
        if (idx < 720)
            asm volatile("cp.async.cg.shared.global [%0], [%1], 16;"
                         :: "r"(s + idx * 16), "l"(g + idx * 16));
    }
    CP_COMMIT();
}

// ---------------------------------------------------------------------------
// Precompute P1 (measured ~10.5us): Wc = Wu@Wm + bc.
// ---------------------------------------------------------------------------
__global__ void precompWc(const float* __restrict__ Wm, const float* __restrict__ bm,
                          const float* __restrict__ Wu, const float* __restrict__ bu, int K)
{
    extern __shared__ float sWm[];   // 128*128 floats (64 KB)
    __shared__ float sWu[D_];
    const int f = blockIdx.x, tid = threadIdx.x;
    {
        const float4* wm4 = (const float4*)Wm;
        float4* s4 = (float4*)sWm;
        for (int i = tid; i < 4096; i += 128) s4[i] = wm4[i];
    }
    sWu[tid] = Wu[f * D_ + tid];
    __syncthreads();
    float a0 = 0.f, a1 = 0.f, a2 = 0.f, a3 = 0.f;
#pragma unroll
    for (int e = 0; e < D_; e += 4) {
        a0 += sWu[e]     * sWm[e * D_ + tid];
        a1 += sWu[e + 1] * sWm[(e + 1) * D_ + tid];
        a2 += sWu[e + 2] * sWm[(e + 2) * D_ + tid];
        a3 += sWu[e + 3] * sWm[(e + 3) * D_ + tid];
    }
    g_Wc[f * D_ + tid] = (a0 + a1) + (a2 + a3);
    if (tid == 0) {
        float s = 0.f;
        for (int e = 0; e < D_; e++) s += sWu[e] * bm[e];
        g_bc[f] = (float)K * s + bu[f];
    }
}

// ---------------------------------------------------------------------------
// Precompute P2: all 23 fp16 chunks + bias table.
// ---------------------------------------------------------------------------
__global__ void precompChunks(const float* __restrict__ W0, const float* __restrict__ b0,
                              const float* __restrict__ W1, const float* __restrict__ b1,
                              const float* __restrict__ W2, const float* __restrict__ b2,
                              const float* __restrict__ W3, const float* __restrict__ b3)
{
    __shared__ float sm1[128 * 32];   // Wc slice [f][kk]
    __shared__ float sm2[132 * 32];   // folded Wcat slice [n][kk]
    const int cid = blockIdx.x, tid = threadIdx.x;
    int l, c;
    if (cid < 8) { l = 0; c = cid; } else { l = 1 + (cid - 8) / 5; c = (cid - 8) % 5; }

    if (l == 0 && c == 0) {
        for (int t = tid; t < 144; t += 256) {
            float bv = 0.f;
            if (t < H_) {
                bv = b0[t];
                float s0 = 0.f, s1 = 0.f;
#pragma unroll 8
                for (int f = 0; f < 128; f += 2) {
                    s0 += W0[t * 256 + 128 + f]     * g_bc[f];
                    s1 += W0[t * 256 + 128 + f + 1] * g_bc[f + 1];
                }
                bv += s0 + s1;
            }
            g_biasf[0][t] = bv;
        }
    } else if (c == 0) {
        const float* bb = (l == 1) ? b1 : (l == 2) ? b2 : b3;
        const int Nl = (l == 3) ? D_ : H_;
        for (int t = tid; t < 144; t += 256) g_biasf[l][t] = (t < Nl) ? bb[t] : 0.f;
    }

    if (l == 0 && c >= 4) {
        const int base = c * 32 - 128;
        for (int idx = tid; idx < 128 * 32; idx += 256) {
            int f = idx >> 5, kk = idx & 31;
            sm1[idx] = g_Wc[f * D_ + base + kk];
        }
        __syncthreads();
        for (int idx = tid; idx < 132 * 32; idx += 256) {
            int n = idx >> 5, kk = idx & 31;
            float s0 = 0.f, s1 = 0.f;
#pragma unroll 8
            for (int f = 0; f < 128; f += 2) {
                s0 += W0[n * 256 + 128 + f]     * sm1[f * 32 + kk];
                s1 += W0[n * 256 + 128 + f + 1] * sm1[(f + 1) * 32 + kk];
            }
            sm2[idx] = s0 + s1;
        }
        __syncthreads();
    }

    const int Kl = (l == 0) ? 256 : H_;
    const int Nl = (l == 3) ? D_ : H_;
    for (int idx = tid; idx < 144 * 40; idx += 256) {
        int n = idx / 40, kk = idx % 40;
        int k = c * 32 + kk;
        float w = 0.f;
        if (kk < 32 && n < Nl && k < Kl) {
            if (l == 0)      w = (c < 4) ? W0[n * 256 + k] : sm2[n * 32 + kk];
            else if (l == 1) w = W1[n * H_ + k];
            else if (l == 2) w = W2[n * H_ + k];
            else             w = W3[n * H_ + k];
        }
        g_Bw[cid][idx] = __float2half_rn(w);
    }
}

// ---------------------------------------------------------------------------
// A-tile loader: signal cols 0-127, csum cols 128-255, split hi/lo fp16.
// ---------------------------------------------------------------------------
__device__ __forceinline__ void load_tile(char* smem, int abase, long rbase,
                                          const float4* __restrict__ sig4,
                                          const float4* __restrict__ cmp4,
                                          long sK, int t0, int nthr)
{
    for (int idx = t0; idx < 2048; idx += nthr) {
        int half = idx >> 10, t = idx & 1023;
        int r = t >> 4, g = t & 15;
        long ga = (rbase + r) * 32 + g * 2;
        float4 v0, v1;
        if (half == 0) { v0 = sig4[ga]; v1 = sig4[ga + 1]; }
        else {
            v0 = make_float4(0.f, 0.f, 0.f, 0.f); v1 = v0;
#pragma unroll 8
            for (int k = 0; k < 8; k++) {
                float4 a = cmp4[ga + (long)k * sK];
                float4 b = cmp4[ga + 1 + (long)k * sK];
                v0.x += a.x; v0.y += a.y; v0.z += a.z; v0.w += a.w;
                v1.x += b.x; v1.y += b.y; v1.z += b.z; v1.w += b.w;
            }
        }
        float f[8] = {v0.x, v0.y, v0.z, v0.w, v1.x, v1.y, v1.z, v1.w};
        uint32_t hh[4], ll[4];
#pragma unroll
        for (int j = 0; j < 4; j++) {
            __half h0, l0, h1, l1;
            split_f16(f[2 * j], h0, l0);
            split_f16(f[2 * j + 1], h1, l1);
            hh[j] = pack2h(h0, h1);
            ll[j] = pack2h(l0, l1);
        }
        int cols = half * 128 + g * 8;
        *(uint4*)(smem + abase + r * ASTRIDE + cols * 2)            = make_uint4(hh[0], hh[1], hh[2], hh[3]);
        *(uint4*)(smem + abase + A_LO_OFF + r * ASTRIDE + cols * 2) = make_uint4(ll[0], ll[1], ll[2], ll[3]);
    }
}

// ---------------------------------------------------------------------------
// One layer (4 consumer warps, 16-row slab each, all N). 2-term fp16,
// RAW pairs separated (Ah pass then Al pass per GS=6 group).
// B: 3-buffer cp.async pipeline, 2 chunks in flight, wait_group 1.
// bq = running buffer index mod 3 (persists across layers and tiles).
// ---------------------------------------------------------------------------
template<int NT, int NC, bool RELU, bool LAST, bool ZPAD>
__device__ __forceinline__ void run_layer(char* smem, uint32_t sb, int layer, int& cid,
                                          int& bq, bool more, int abase,
                                          int tid, int wid, int lane,
                                          float* __restrict__ gout)
{
    constexpr int GS = 6;
    constexpr int NG = (NT + GS - 1) / GS;

    float acc[NT][4];
#pragma unroll
    for (int t = 0; t < NT; t++)
#pragma unroll
        for (int j = 0; j < 4; j++) acc[t][j] = 0.f;

    const int R0 = wid * 16;
    const int ln = lane & 15;
    const uint32_t aAh0 = sb + abase + (uint32_t)(R0 + ln) * ASTRIDE + (uint32_t)(lane >> 4) * 16;
    const uint32_t bB0  = sb + B_OFF + (uint32_t)(ln & 7) * BSTRIDE + (uint32_t)(ln >> 3) * 16;

    for (int c = 0; c < NC; c++) {
        CP_WAIT1();            // chunk cid staged (one group may remain in flight)
        BAR_CONS();            // cross-thread visibility + buffer release
        {
            int nb = cid + 2;
            int wq = bq + 2; if (wq >= 3) wq -= 3;
            if (nb < NCHUNK)   stage_chunk(sb, nb, wq, tid);
            else if (more)     stage_chunk(sb, nb - NCHUNK, wq, tid);
        }
        const uint32_t bbuf = bB0 + (uint32_t)bq * B_BUF;
        const uint32_t ak   = aAh0 + (uint32_t)c * 64;
#pragma unroll
        for (int s = 0; s < 2; s++) {
            uint32_t Ah[4], Al[4];
            LDSM4(Ah, ak + s * 32);
            LDSM4(Al, ak + s * 32 + A_LO_OFF);

            uint32_t Bf[2][GS][2];
#pragma unroll
            for (int j = 0; j < GS; j++)
                if (j < NT) LDSM2(Bf[0][j], bbuf + (uint32_t)j * (8 * BSTRIDE) + s * 32);
#pragma unroll
            for (int g = 0; g < NG; g++) {
                const int cu = g & 1, nx = cu ^ 1;
                if (g + 1 < NG) {
#pragma unroll
                    for (int j = 0; j < GS; j++) {
                        const int t = (g + 1) * GS + j;
                        if (t < NT) LDSM2(Bf[nx][j], bbuf + (uint32_t)t * (8 * BSTRIDE) + s * 32);
                    }
                }
                // pass 1: all Ah MMAs of this group (mutually independent)
#pragma unroll
                for (int j = 0; j < GS; j++) {
                    const int t = g * GS + j;
                    if (t < NT) MMA(acc[t], Ah, Bf[cu][j]);
                }
                // pass 2: all Al MMAs (6 issue slots after their RAW producers)
#pragma unroll
                for (int j = 0; j < GS; j++) {
                    const int t = g * GS + j;
                    if (t < NT) MMA(acc[t], Al, Bf[cu][j]);
                }
            }
        }
        cid++;
        bq = (bq == 2) ? 0 : bq + 1;
    }

    // ---- epilogue (warp-private rows); bias from SMEM (broadcast LDS)
    const float* bias = (const float*)(smem + BIAS_OFF) + layer * 144;
    const int r0 = R0 + (lane >> 2);
#pragma unroll
    for (int t = 0; t < NT; t++) {
        const int col = t * 8 + (lane & 3) * 2;
        const float2 bv = *(const float2*)(bias + col);
        float v00 = acc[t][0] + bv.x, v01 = acc[t][1] + bv.y;
        float v10 = acc[t][2] + bv.x, v11 = acc[t][3] + bv.y;
        if (RELU) {
            v00 = fmaxf(v00, 0.f); v01 = fmaxf(v01, 0.f);
            v10 = fmaxf(v10, 0.f); v11 = fmaxf(v11, 0.f);
        }
        if (LAST) {
            *(float2*)(gout + (long)r0 * D_ + col)       = make_float2(v00, v01);
            *(float2*)(gout + (long)(r0 + 8) * D_ + col) = make_float2(v10, v11);
        } else {
            __half h0, l0, h1, l1;
            split_f16(v00, h0, l0); split_f16(v01, h1, l1);
            *(uint32_t*)(smem + abase + r0 * ASTRIDE + col * 2)            = pack2h(h0, h1);
            *(uint32_t*)(smem + abase + A_LO_OFF + r0 * ASTRIDE + col * 2) = pack2h(l0, l1);
            split_f16(v10, h0, l0); split_f16(v11, h1, l1);
            *(uint32_t*)(smem + abase + (r0 + 8) * ASTRIDE + col * 2)            = pack2h(h0, h1);
            *(uint32_t*)(smem + abase + A_LO_OFF + (r0 + 8) * ASTRIDE + col * 2) = pack2h(l0, l1);
        }
    }
    if (ZPAD) {   // zero activation K-pad cols 144..159 (hi & lo)
        const int zr = R0 + (lane >> 1);
        const int zc = 144 + (lane & 1) * 8;
        uint4 z = make_uint4(0u, 0u, 0u, 0u);
        *(uint4*)(smem + abase + zr * ASTRIDE + zc * 2)            = z;
        *(uint4*)(smem + abase + A_LO_OFF + zr * ASTRIDE + zc * 2) = z;
    }
    __syncwarp();
}

// ---------------------------------------------------------------------------
// Persistent warp-specialized kernel: warps 0-3 compute, warps 4-7 load next tile
// ---------------------------------------------------------------------------
__global__ __launch_bounds__(TPB, 1)
void fused_mma(const float* __restrict__ sig, const float* __restrict__ comps,
               float* __restrict__ out, int Bn, int K)
{
    extern __shared__ __align__(16) char smem[];
    const uint32_t sb = smem_u32(smem);
    const int tid = threadIdx.x, wid = tid >> 5, lane = tid & 31;
    const int G = gridDim.x;
    const int ntiles = Bn / M_;

    const float4* sig4 = (const float4*)sig;
    const float4* cmp4 = (const float4*)comps;
    const long sK = (long)Bn * 32;

    // bias table to SMEM (once per CTA)
    for (int j = tid; j < 576; j += TPB)
        ((float*)(smem + BIAS_OFF))[j] = ((const float*)g_biasf)[j];

    // prologue: all 256 threads load first tile; consumers stage chunks 0,1
    load_tile(smem, 0, (long)blockIdx.x * M_, sig4, cmp4, sK, tid, TPB);
    if (tid < 128) {
        stage_chunk(sb, 0, 0, tid);
        stage_chunk(sb, 1, 1, tid);
    }
    __syncthreads();

    int i = 0;
    int bq = 0;   // running B buffer index (consumer threads; deterministic)
    for (int t = blockIdx.x; t < ntiles; t += G, i++) {
        if (tid < 128) {
            const int abase = (i & 1) * ABUFSZ;
            const bool more = (t + G < ntiles);
            float* gout = out + (long)t * M_ * D_;
            int cid = 0;
            run_layer<18, 8, true,  false, true >(smem, sb, 0, cid, bq, true, abase, tid, wid, lane, nullptr);
            run_layer<18, 5, true,  false, false>(smem, sb, 1, cid, bq, true, abase, tid, wid, lane, nullptr);
            run_layer<18, 5, true,  false, false>(smem, sb, 2, cid, bq, true, abase, tid, wid, lane, nullptr);
            run_layer<16, 5, false, true,  false>(smem, sb, 3, cid, bq, more, abase, tid, wid, lane, gout);
        } else {
            long tn = (long)t + G;
            if (tn < ntiles)
                load_tile(smem, ((i + 1) & 1) * ABUFSZ, tn * M_, sig4, cmp4, sK, tid - 128, 128);
        }
        __syncthreads();   // tile boundary: A buffers exchange ownership
    }
}

// ---------------------------------------------------------------------------
extern "C" void kernel_launch(void* const* d_in, const int* in_sizes, int n_in,
                              void* d_out, int out_size)
{
    const float* sig   = (const float*)d_in[0];
    const float* comps = (const float*)d_in[1];
    const float* Wm    = (const float*)d_in[2];
    const float* bm    = (const float*)d_in[3];
    const float* Wu    = (const float*)d_in[4];
    const float* bu    = (const float*)d_in[5];
    const float* W0    = (const float*)d_in[6];
    const float* b0    = (const float*)d_in[7];
    const float* W1    = (const float*)d_in[8];
    const float* b1    = (const float*)d_in[9];
    const float* W2    = (const float*)d_in[10];
    const float* b2    = (const float*)d_in[11];
    const float* W3    = (const float*)d_in[12];
    const float* b3    = (const float*)d_in[13];
    float* out = (float*)d_out;

    const int B = in_sizes[0] / D_;           // 65536
    const int K = in_sizes[1] / in_sizes[0];  // 8

    int nsm = 148;
    cudaDeviceGetAttribute(&nsm, cudaDevAttrMultiProcessorCount, 0);

    cudaFuncSetAttribute(fused_mma,
                         cudaFuncAttributeMaxDynamicSharedMemorySize, SMEM_BYTES);
    cudaFuncSetAttribute(precompWc,
                         cudaFuncAttributeMaxDynamicSharedMemorySize, 65536);

    precompWc<<<D_, D_, 65536>>>(Wm, bm, Wu, bu, K);
    precompChunks<<<NCHUNK, 256>>>(W0, b0, W1, b1, W2, b2, W3, b3);
    fused_mma<<<nsm, TPB, SMEM_BYTES>>>(sig, comps, out, B, K);
}

// round 17
// speedup vs baseline: 1.2322x; 1.0777x over previous
#include <cuda_runtime.h>
#include <cuda_bf16.h>
#include <cuda_fp16.h>
#include <cstdint>

#define D_  128
#define H_  132
#define M_  64       // batch rows per tile
#define TPB 256      // 4 compute warps + 4 producer warps

// ---------------------------------------------------------------------------
// Device-global precomputed buffers
// ---------------------------------------------------------------------------
__device__ float g_Wc[D_ * D_];   // Wu @ Wm
__device__ float g_bc[D_];        // K*(Wu@bm) + bu
// 23 weight chunks (L0:8, L1:5, L2:5, L3:5), each [144 n][40 k] fp16
__device__ __align__(16) __half g_Bw[23][144 * 40];
__device__ float g_biasf[4][144];

// ---------------------------------------------------------------------------
// SMEM map (bytes)
//   A buf0 fp16 [64][264] (row stride 528B) :      0 .. 33792
//   A buf1                                   :  33792 .. 67584
//   B buf x3 (fp16, 11520 each)              :  67584 .. 102144
//   bias [4][144] f32                        : 102144 .. 104448
// ---------------------------------------------------------------------------
#define ABUFSZ   33792
#define ASTRIDE  528
#define B_OFF    67584
#define B_BUF    11520
#define BSTRIDE  80
#define BIAS_OFF 102144
#define SMEM_BYTES 104448
#define NCHUNK   23

// ---------------------------------------------------------------------------
// PTX helpers (plain sm_80+ features only)
// ---------------------------------------------------------------------------
__device__ __forceinline__ uint32_t smem_u32(const void* p) {
    uint32_t a;
    asm("{ .reg .u64 t; cvta.to.shared.u64 t, %1; cvt.u32.u64 %0, t; }" : "=r"(a) : "l"(p));
    return a;
}
#define LDSM4(r, a) \
    asm volatile("ldmatrix.sync.aligned.m8n8.x4.shared.b16 {%0,%1,%2,%3}, [%4];" \
                 : "=r"((r)[0]), "=r"((r)[1]), "=r"((r)[2]), "=r"((r)[3]) : "r"(a))
#define LDSM2(r, a) \
    asm volatile("ldmatrix.sync.aligned.m8n8.x2.shared.b16 {%0,%1}, [%2];" \
                 : "=r"((r)[0]), "=r"((r)[1]) : "r"(a))
#define MMA(c, A, Bv) \
    asm volatile("mma.sync.aligned.m16n8k16.row.col.f32.f16.f16.f32 " \
                 "{%0,%1,%2,%3}, {%4,%5,%6,%7}, {%8,%9}, {%0,%1,%2,%3};" \
                 : "+f"((c)[0]), "+f"((c)[1]), "+f"((c)[2]), "+f"((c)[3]) \
                 : "r"((A)[0]), "r"((A)[1]), "r"((A)[2]), "r"((A)[3]), \
                   "r"((Bv)[0]), "r"((Bv)[1]))
#define CP_WAIT1()  asm volatile("cp.async.wait_group 1;" ::: "memory")
#define CP_COMMIT() asm volatile("cp.async.commit_group;" ::: "memory")
#define BAR_CONS()  asm volatile("bar.sync 1, 128;" ::: "memory")

__device__ __forceinline__ uint32_t pack2h(__half a, __half b) {
    uint16_t x = *(uint16_t*)&a, y = *(uint16_t*)&b;
    return (uint32_t)x | ((uint32_t)y << 16);
}

// stage fp16 weight chunk cid into B buf `buf` (720 x 16B, 128 consumer threads)
__device__ __forceinline__ void stage_chunk(uint32_t sb, int cid, int buf, int tid128) {
    const char* g = (const char*)&g_Bw[cid][0];
    uint32_t s = sb + B_OFF + (uint32_t)buf * B_BUF;
#pragma unroll
    for (int j = 0; j < 6; j++) {
        int idx = tid128 + j * 128;
        if (idx < 720)
            asm volatile("cp.async.cg.shared.global [%0], [%1], 16;"
                         :: "r"(s + idx * 16), "l"(g + idx * 16));
    }
    CP_COMMIT();
}

// ---------------------------------------------------------------------------
// Precompute P1 (measured ~10.5us): Wc = Wu@Wm + bc.
// ---------------------------------------------------------------------------
__global__ void precompWc(const float* __restrict__ Wm, const float* __restrict__ bm,
                          const float* __restrict__ Wu, const float* __restrict__ bu, int K)
{
    extern __shared__ float sWm[];   // 128*128 floats (64 KB)
    __shared__ float sWu[D_];
    const int f = blockIdx.x, tid = threadIdx.x;
    {
        const float4* wm4 = (const float4*)Wm;
        float4* s4 = (float4*)sWm;
        for (int i = tid; i < 4096; i += 128) s4[i] = wm4[i];
    }
    sWu[tid] = Wu[f * D_ + tid];
    __syncthreads();
    float a0 = 0.f, a1 = 0.f, a2 = 0.f, a3 = 0.f;
#pragma unroll
    for (int e = 0; e < D_; e += 4) {
        a0 += sWu[e]     * sWm[e * D_ + tid];
        a1 += sWu[e + 1] * sWm[(e + 1) * D_ + tid];
        a2 += sWu[e + 2] * sWm[(e + 2) * D_ + tid];
        a3 += sWu[e + 3] * sWm[(e + 3) * D_ + tid];
    }
    g_Wc[f * D_ + tid] = (a0 + a1) + (a2 + a3);
    if (tid == 0) {
        float s = 0.f;
        for (int e = 0; e < D_; e++) s += sWu[e] * bm[e];
        g_bc[f] = (float)K * s + bu[f];
    }
}

// ---------------------------------------------------------------------------
// Precompute P2: all 23 fp16 chunks + bias table.
// ---------------------------------------------------------------------------
__global__ void precompChunks(const float* __restrict__ W0, const float* __restrict__ b0,
                              const float* __restrict__ W1, const float* __restrict__ b1,
                              const float* __restrict__ W2, const float* __restrict__ b2,
                              const float* __restrict__ W3, const float* __restrict__ b3)
{
    __shared__ float sm1[128 * 32];   // Wc slice [f][kk]
    __shared__ float sm2[132 * 32];   // folded Wcat slice [n][kk]
    const int cid = blockIdx.x, tid = threadIdx.x;
    int l, c;
    if (cid < 8) { l = 0; c = cid; } else { l = 1 + (cid - 8) / 5; c = (cid - 8) % 5; }

    if (l == 0 && c == 0) {
        for (int t = tid; t < 144; t += 256) {
            float bv = 0.f;
            if (t < H_) {
                bv = b0[t];
                float s0 = 0.f, s1 = 0.f;
#pragma unroll 8
                for (int f = 0; f < 128; f += 2) {
                    s0 += W0[t * 256 + 128 + f]     * g_bc[f];
                    s1 += W0[t * 256 + 128 + f + 1] * g_bc[f + 1];
                }
                bv += s0 + s1;
            }
            g_biasf[0][t] = bv;
        }
    } else if (c == 0) {
        const float* bb = (l == 1) ? b1 : (l == 2) ? b2 : b3;
        const int Nl = (l == 3) ? D_ : H_;
        for (int t = tid; t < 144; t += 256) g_biasf[l][t] = (t < Nl) ? bb[t] : 0.f;
    }

    if (l == 0 && c >= 4) {
        const int base = c * 32 - 128;
        for (int idx = tid; idx < 128 * 32; idx += 256) {
            int f = idx >> 5, kk = idx & 31;
            sm1[idx] = g_Wc[f * D_ + base + kk];
        }
        __syncthreads();
        for (int idx = tid; idx < 132 * 32; idx += 256) {
            int n = idx >> 5, kk = idx & 31;
            float s0 = 0.f, s1 = 0.f;
#pragma unroll 8
            for (int f = 0; f < 128; f += 2) {
                s0 += W0[n * 256 + 128 + f]     * sm1[f * 32 + kk];
                s1 += W0[n * 256 + 128 + f + 1] * sm1[(f + 1) * 32 + kk];
            }
            sm2[idx] = s0 + s1;
        }
        __syncthreads();
    }

    const int Kl = (l == 0) ? 256 : H_;
    const int Nl = (l == 3) ? D_ : H_;
    for (int idx = tid; idx < 144 * 40; idx += 256) {
        int n = idx / 40, kk = idx % 40;
        int k = c * 32 + kk;
        float w = 0.f;
        if (kk < 32 && n < Nl && k < Kl) {
            if (l == 0)      w = (c < 4) ? W0[n * 256 + k] : sm2[n * 32 + kk];
            else if (l == 1) w = W1[n * H_ + k];
            else if (l == 2) w = W2[n * H_ + k];
            else             w = W3[n * H_ + k];
        }
        g_Bw[cid][idx] = __float2half_rn(w);
    }
}

// ---------------------------------------------------------------------------
// A-tile loader: signal cols 0-127, csum cols 128-255, single fp16.
// ---------------------------------------------------------------------------
__device__ __forceinline__ void load_tile(char* smem, int abase, long rbase,
                                          const float4* __restrict__ sig4,
                                          const float4* __restrict__ cmp4,
                                          long sK, int t0, int nthr)
{
    for (int idx = t0; idx < 2048; idx += nthr) {
        int half = idx >> 10, t = idx & 1023;
        int r = t >> 4, g = t & 15;
        long ga = (rbase + r) * 32 + g * 2;
        float4 v0, v1;
        if (half == 0) { v0 = sig4[ga]; v1 = sig4[ga + 1]; }
        else {
            v0 = make_float4(0.f, 0.f, 0.f, 0.f); v1 = v0;
#pragma unroll 8
            for (int k = 0; k < 8; k++) {
                float4 a = cmp4[ga + (long)k * sK];
                float4 b = cmp4[ga + 1 + (long)k * sK];
                v0.x += a.x; v0.y += a.y; v0.z += a.z; v0.w += a.w;
                v1.x += b.x; v1.y += b.y; v1.z += b.z; v1.w += b.w;
            }
        }
        uint32_t hh[4];
        hh[0] = pack2h(__float2half_rn(v0.x), __float2half_rn(v0.y));
        hh[1] = pack2h(__float2half_rn(v0.z), __float2half_rn(v0.w));
        hh[2] = pack2h(__float2half_rn(v1.x), __float2half_rn(v1.y));
        hh[3] = pack2h(__float2half_rn(v1.z), __float2half_rn(v1.w));
        int cols = half * 128 + g * 8;
        *(uint4*)(smem + abase + r * ASTRIDE + cols * 2) = make_uint4(hh[0], hh[1], hh[2], hh[3]);
    }
}

// ---------------------------------------------------------------------------
// One layer (4 consumer warps, 16-row slab each, all N). Single-term fp16:
// acc += A*B. B loads batched in register-double-buffered GS=6 groups.
// B: 3-buffer cp.async pipeline, 2 chunks in flight, wait_group 1.
// ---------------------------------------------------------------------------
template<int NT, int NC, bool RELU, bool LAST, bool ZPAD>
__device__ __forceinline__ void run_layer(char* smem, uint32_t sb, int layer, int& cid,
                                          int& bq, bool more, int abase,
                                          int tid, int wid, int lane,
                                          float* __restrict__ gout)
{
    constexpr int GS = 6;
    constexpr int NG = (NT + GS - 1) / GS;

    float acc[NT][4];
#pragma unroll
    for (int t = 0; t < NT; t++)
#pragma unroll
        for (int j = 0; j < 4; j++) acc[t][j] = 0.f;

    const int R0 = wid * 16;
    const int ln = lane & 15;
    const uint32_t aA0 = sb + abase + (uint32_t)(R0 + ln) * ASTRIDE + (uint32_t)(lane >> 4) * 16;
    const uint32_t bB0 = sb + B_OFF + (uint32_t)(ln & 7) * BSTRIDE + (uint32_t)(ln >> 3) * 16;

    for (int c = 0; c < NC; c++) {
        CP_WAIT1();            // chunk cid staged (one group may remain in flight)
        BAR_CONS();            // cross-thread visibility + buffer release
        {
            int nb = cid + 2;
            int wq = bq + 2; if (wq >= 3) wq -= 3;
            if (nb < NCHUNK)   stage_chunk(sb, nb, wq, tid);
            else if (more)     stage_chunk(sb, nb - NCHUNK, wq, tid);
        }
        const uint32_t bbuf = bB0 + (uint32_t)bq * B_BUF;
        const uint32_t ak   = aA0 + (uint32_t)c * 64;
#pragma unroll
        for (int s = 0; s < 2; s++) {
            uint32_t Ah[4];
            LDSM4(Ah, ak + s * 32);

            uint32_t Bf[2][GS][2];
#pragma unroll
            for (int j = 0; j < GS; j++)
                if (j < NT) LDSM2(Bf[0][j], bbuf + (uint32_t)j * (8 * BSTRIDE) + s * 32);
#pragma unroll
            for (int g = 0; g < NG; g++) {
                const int cu = g & 1, nx = cu ^ 1;
                if (g + 1 < NG) {
#pragma unroll
                    for (int j = 0; j < GS; j++) {
                        const int t = (g + 1) * GS + j;
                        if (t < NT) LDSM2(Bf[nx][j], bbuf + (uint32_t)t * (8 * BSTRIDE) + s * 32);
                    }
                }
#pragma unroll
                for (int j = 0; j < GS; j++) {
                    const int t = g * GS + j;
                    if (t < NT) MMA(acc[t], Ah, Bf[cu][j]);
                }
            }
        }
        cid++;
        bq = (bq == 2) ? 0 : bq + 1;
    }

    // ---- epilogue (warp-private rows); bias from SMEM (broadcast LDS)
    const float* bias = (const float*)(smem + BIAS_OFF) + layer * 144;
    const int r0 = R0 + (lane >> 2);
#pragma unroll
    for (int t = 0; t < NT; t++) {
        const int col = t * 8 + (lane & 3) * 2;
        const float2 bv = *(const float2*)(bias + col);
        float v00 = acc[t][0] + bv.x, v01 = acc[t][1] + bv.y;
        float v10 = acc[t][2] + bv.x, v11 = acc[t][3] + bv.y;
        if (RELU) {
            v00 = fmaxf(v00, 0.f); v01 = fmaxf(v01, 0.f);
            v10 = fmaxf(v10, 0.f); v11 = fmaxf(v11, 0.f);
        }
        if (LAST) {
            *(float2*)(gout + (long)r0 * D_ + col)       = make_float2(v00, v01);
            *(float2*)(gout + (long)(r0 + 8) * D_ + col) = make_float2(v10, v11);
        } else {
            *(uint32_t*)(smem + abase + r0 * ASTRIDE + col * 2) =
                pack2h(__float2half_rn(v00), __float2half_rn(v01));
            *(uint32_t*)(smem + abase + (r0 + 8) * ASTRIDE + col * 2) =
                pack2h(__float2half_rn(v10), __float2half_rn(v11));
        }
    }
    if (ZPAD) {   // zero activation K-pad cols 144..159 of this warp's 16 rows
        const int zr = R0 + (lane >> 1);
        const int zc = 144 + (lane & 1) * 8;
        *(uint4*)(smem + abase + zr * ASTRIDE + zc * 2) = make_uint4(0u, 0u, 0u, 0u);
    }
    __syncwarp();
}

// ---------------------------------------------------------------------------
// Persistent warp-specialized kernel: warps 0-3 compute, warps 4-7 load next tile
// ---------------------------------------------------------------------------
__global__ __launch_bounds__(TPB, 1)
void fused_mma(const float* __restrict__ sig, const float* __restrict__ comps,
               float* __restrict__ out, int Bn, int K)
{
    extern __shared__ __align__(16) char smem[];
    const uint32_t sb = smem_u32(smem);
    const int tid = threadIdx.x, wid = tid >> 5, lane = tid & 31;
    const int G = gridDim.x;
    const int ntiles = Bn / M_;

    const float4* sig4 = (const float4*)sig;
    const float4* cmp4 = (const float4*)comps;
    const long sK = (long)Bn * 32;

    // bias table to SMEM (once per CTA)
    for (int j = tid; j < 576; j += TPB)
        ((float*)(smem + BIAS_OFF))[j] = ((const float*)g_biasf)[j];

    // prologue: all 256 threads load first tile; consumers stage chunks 0,1
    load_tile(smem, 0, (long)blockIdx.x * M_, sig4, cmp4, sK, tid, TPB);
    if (tid < 128) {
        stage_chunk(sb, 0, 0, tid);
        stage_chunk(sb, 1, 1, tid);
    }
    __syncthreads();

    int i = 0;
    int bq = 0;   // running B buffer index (consumer threads; deterministic)
    for (int t = blockIdx.x; t < ntiles; t += G, i++) {
        if (tid < 128) {
            const int abase = (i & 1) * ABUFSZ;
            const bool more = (t + G < ntiles);
            float* gout = out + (long)t * M_ * D_;
            int cid = 0;
            run_layer<18, 8, true,  false, true >(smem, sb, 0, cid, bq, true, abase, tid, wid, lane, nullptr);
            run_layer<18, 5, true,  false, false>(smem, sb, 1, cid, bq, true, abase, tid, wid, lane, nullptr);
            run_layer<18, 5, true,  false, false>(smem, sb, 2, cid, bq, true, abase, tid, wid, lane, nullptr);
            run_layer<16, 5, false, true,  false>(smem, sb, 3, cid, bq, more, abase, tid, wid, lane, gout);
        } else {
            long tn = (long)t + G;
            if (tn < ntiles)
                load_tile(smem, ((i + 1) & 1) * ABUFSZ, tn * M_, sig4, cmp4, sK, tid - 128, 128);
        }
        __syncthreads();   // tile boundary: A buffers exchange ownership
    }
}

// ---------------------------------------------------------------------------
extern "C" void kernel_launch(void* const* d_in, const int* in_sizes, int n_in,
                              void* d_out, int out_size)
{
    const float* sig   = (const float*)d_in[0];
    const float* comps = (const float*)d_in[1];
    const float* Wm    = (const float*)d_in[2];
    const float* bm    = (const float*)d_in[3];
    const float* Wu    = (const float*)d_in[4];
    const float* bu    = (const float*)d_in[5];
    const float* W0    = (const float*)d_in[6];
    const float* b0    = (const float*)d_in[7];
    const float* W1    = (const float*)d_in[8];
    const float* b1    = (const float*)d_in[9];
    const float* W2    = (const float*)d_in[10];
    const float* b2    = (const float*)d_in[11];
    const float* W3    = (const float*)d_in[12];
    const float* b3    = (const float*)d_in[13];
    float* out = (float*)d_out;

    const int B = in_sizes[0] / D_;           // 65536
    const int K = in_sizes[1] / in_sizes[0];  // 8

    int nsm = 148;
    cudaDeviceGetAttribute(&nsm, cudaDevAttrMultiProcessorCount, 0);

    cudaFuncSetAttribute(fused_mma,
                         cudaFuncAttributeMaxDynamicSharedMemorySize, SMEM_BYTES);
    cudaFuncSetAttribute(precompWc,
                         cudaFuncAttributeMaxDynamicSharedMemorySize, 65536);

    precompWc<<<D_, D_, 65536>>>(Wm, bm, Wu, bu, K);
    precompChunks<<<NCHUNK, 256>>>(W0, b0, W1, b1, W2, b2, W3, b3);
    fused_mma<<<nsm, TPB, SMEM_BYTES>>>(sig, comps, out, B, K);
}